// round 1
// baseline (speedup 1.0000x reference)
#include <cuda_runtime.h>
#include <math.h>

// ---------------- problem constants ----------------
#define T_SEQ   2048
#define DMODEL  2048
#define NH      16
#define NKV     4
#define DH      128
#define BATCH   2
#define NROWS   (BATCH * T_SEQ)   // 4096
#define TKEYS   1152              // META + min(WINDOW, T-META) = 128 + 1024

// ---------------- scratch (device globals; no runtime alloc) ----------------
__device__ float g_q [(size_t)NROWS * DMODEL];      // post-RoPE Q  [row][h*128+d]
__device__ float g_k [(size_t)NROWS * (NKV * DH)];  // post-RoPE K  [row][kv*128+d]
__device__ float g_v [(size_t)NROWS * (NKV * DH)];
__device__ float g_ao[(size_t)NROWS * DMODEL];      // attention out [row][h*128+d]
__device__ float g_rc[T_SEQ * 64];                  // rope cos [t][j]
__device__ float g_rs[T_SEQ * 64];                  // rope sin [t][j]

// ---------------- RoPE table (double precision, tiny) ----------------
__global__ void rope_table_kernel() {
    int idx = blockIdx.x * 256 + threadIdx.x;       // 2048*64 = 131072
    if (idx >= T_SEQ * 64) return;
    int t = idx >> 6;
    int j = idx & 63;
    double inv = pow(10000.0, -(double)j / 64.0);
    double f   = (double)t * inv;
    g_rc[idx] = (float)cos(f);
    g_rs[idx] = (float)sin(f);
}

// ---------------- SGEMM: C[M=4096,N] = A[4096,2048] @ W[2048,N], optional RoPE epilogue ----------------
// 128x128 block tile, BK=8, 256 threads, 8x8 microtile (4x4 quadrants), double-buffered smem.
__global__ __launch_bounds__(256, 2)
void sgemm_kernel(const float* __restrict__ A, const float* __restrict__ W,
                  float* __restrict__ C, int N, int doRope) {
    const int K = DMODEL;
    __shared__ float As[2][8][128];   // [buf][kk][row]  (A stored transposed)
    __shared__ float Bs[2][8][128];   // [buf][kk][col]

    int tid = threadIdx.x;
    int tx = tid & 15, ty = tid >> 4;
    int bm = blockIdx.y * 128;
    int bn = blockIdx.x * 128;

    int arow = tid >> 1;              // 0..127
    int akg  = (tid & 1) << 2;        // 0 or 4
    int brow = tid >> 5;              // 0..7
    int bcol = (tid & 31) << 2;       // 0..124

    const float* Ap = A + (size_t)(bm + arow) * K + akg;
    const float* Wp = W + (size_t)brow * N + bn + bcol;

    float4 aR = *(const float4*)Ap;
    float4 bR = *(const float4*)Wp;

    float acc[8][8];
#pragma unroll
    for (int i = 0; i < 8; i++)
#pragma unroll
        for (int j = 0; j < 8; j++) acc[i][j] = 0.f;

    As[0][akg + 0][arow] = aR.x;
    As[0][akg + 1][arow] = aR.y;
    As[0][akg + 2][arow] = aR.z;
    As[0][akg + 3][arow] = aR.w;
    *(float4*)&Bs[0][brow][bcol] = bR;
    __syncthreads();

    const int nIter = K / 8;          // 256
    int buf = 0;
    for (int it = 0; it < nIter; ++it) {
        if (it + 1 < nIter) {
            aR = *(const float4*)(Ap + (it + 1) * 8);
            bR = *(const float4*)(Wp + (size_t)(it + 1) * 8 * N);
        }
#pragma unroll
        for (int kk = 0; kk < 8; kk++) {
            float a[8], b[8];
            *(float4*)&a[0] = *(const float4*)&As[buf][kk][ty * 4];
            *(float4*)&a[4] = *(const float4*)&As[buf][kk][ty * 4 + 64];
            *(float4*)&b[0] = *(const float4*)&Bs[buf][kk][tx * 4];
            *(float4*)&b[4] = *(const float4*)&Bs[buf][kk][tx * 4 + 64];
#pragma unroll
            for (int i = 0; i < 8; i++)
#pragma unroll
                for (int j = 0; j < 8; j++)
                    acc[i][j] += a[i] * b[j];
        }
        if (it + 1 < nIter) {
            buf ^= 1;
            As[buf][akg + 0][arow] = aR.x;
            As[buf][akg + 1][arow] = aR.y;
            As[buf][akg + 2][arow] = aR.z;
            As[buf][akg + 3][arow] = aR.w;
            *(float4*)&Bs[buf][brow][bcol] = bR;
        }
        __syncthreads();
    }

    // epilogue (+ optional RoPE on interleaved pairs, head dim = 128)
#pragma unroll
    for (int i = 0; i < 8; i++) {
        int row = bm + ty * 4 + (i & 3) + ((i >> 2) << 6);
        int t = row & (T_SEQ - 1);    // row = b*T + t
        float vals[8];
#pragma unroll
        for (int j = 0; j < 8; j++) vals[j] = acc[i][j];
        if (doRope) {
#pragma unroll
            for (int jp = 0; jp < 8; jp += 2) {
                int col = bn + tx * 4 + (jp & 3) + ((jp >> 2) << 6);
                int jj = (col & 127) >> 1;
                float ct = g_rc[(t << 6) + jj];
                float st = g_rs[(t << 6) + jj];
                float e = vals[jp], o = vals[jp + 1];
                vals[jp]     = e * ct - o * st;
                vals[jp + 1] = e * st + o * ct;
            }
        }
        float* Cp = C + (size_t)row * N + bn + tx * 4;
        *(float4*)Cp        = make_float4(vals[0], vals[1], vals[2], vals[3]);
        *(float4*)(Cp + 64) = make_float4(vals[4], vals[5], vals[6], vals[7]);
    }
}

// ---------------- Flash attention: sink(128) + window(1024), mask j > i ----------------
// CTA = (q-tile of 64, head, batch). 256 threads (tx 0..15, ty 0..15).
// smem tiles stored [token][128] with XOR swizzle on the float4 column group:
//   element (row, c4) stored at column group c4 ^ (row>>2)   -> conflict-light LDS.128
#define ATT_SMEM ((3 * 64 * 128 + 64 * 68) * 4)   // 115712 B

__global__ __launch_bounds__(256, 1)
void attn_kernel(const float* __restrict__ gq, const float* __restrict__ gk,
                 const float* __restrict__ gv, float* __restrict__ gout) {
    extern __shared__ float sm[];
    float* q_s = sm;                   // 64*128
    float* k_s = q_s + 64 * 128;
    float* v_s = k_s + 64 * 128;
    float* p_s = v_s + 64 * 128;       // 64*68 (padded, no swizzle)

    int tid = threadIdx.x;
    int tx = tid & 15, ty = tid >> 4;
    int qt = blockIdx.x, h = blockIdx.y, b = blockIdx.z;
    int q0 = qt * 64;
    int kvh = h >> 2;                  // REP = 4
    const float scale = 0.08838834764831845f;   // 1/sqrt(128)
    const float NEG_INF = __int_as_float(0xff800000);

    // load Q tile (pre-scaled), swizzled
    {
        const float* qbase = gq + ((size_t)(b * T_SEQ + q0)) * DMODEL + h * DH;
#pragma unroll
        for (int i = 0; i < 8; i++) {
            int idx = tid + 256 * i;   // 0..2047
            int row = idx >> 5;
            int c4  = idx & 31;
            float4 vq = *(const float4*)(qbase + (size_t)row * DMODEL + c4 * 4);
            vq.x *= scale; vq.y *= scale; vq.z *= scale; vq.w *= scale;
            int sc4 = c4 ^ (row >> 2);
            *(float4*)&q_s[row * 128 + sc4 * 4] = vq;
        }
    }

    float m[4], l[4], o[4][8];
#pragma unroll
    for (int r = 0; r < 4; r++) {
        m[r] = NEG_INF; l[r] = 0.f;
#pragma unroll
        for (int c = 0; c < 8; c++) o[r][c] = 0.f;
    }

    int ntiles = (qt + 1 < 18) ? (qt + 1) : 18;
    for (int jt = 0; jt < ntiles; jt++) {
        int j0 = jt * 64;
        __syncthreads();               // prior PV done with v_s/p_s (also covers q_s on jt=0)
        // load K,V tiles (swizzled)
#pragma unroll
        for (int i = 0; i < 8; i++) {
            int idx = tid + 256 * i;
            int row = idx >> 5;
            int c4  = idx & 31;
            int jg = j0 + row;
            int kpos = (jg < 128) ? jg : (jg + 896);   // sink | window(T-1024..)
            size_t base = ((size_t)(b * T_SEQ + kpos)) * (NKV * DH) + kvh * DH + c4 * 4;
            int sc4 = c4 ^ (row >> 2);
            *(float4*)&k_s[row * 128 + sc4 * 4] = *(const float4*)(gk + base);
            *(float4*)&v_s[row * 128 + sc4 * 4] = *(const float4*)(gv + base);
        }
        __syncthreads();

        // S = Q @ K^T (reduction over d, vectorized float4)
        float s[4][4];
#pragma unroll
        for (int r = 0; r < 4; r++)
#pragma unroll
            for (int c = 0; c < 4; c++) s[r][c] = 0.f;

#pragma unroll 8
        for (int kk4 = 0; kk4 < 32; kk4++) {
            float4 qa[4], kb[4];
#pragma unroll
            for (int r = 0; r < 4; r++)
                qa[r] = *(const float4*)&q_s[(ty * 4 + r) * 128 + ((kk4 ^ ty) << 2)];
#pragma unroll
            for (int c = 0; c < 4; c++)
                kb[c] = *(const float4*)&k_s[(tx * 4 + c) * 128 + ((kk4 ^ tx) << 2)];
#pragma unroll
            for (int r = 0; r < 4; r++)
#pragma unroll
                for (int c = 0; c < 4; c++)
                    s[r][c] += qa[r].x * kb[c].x + qa[r].y * kb[c].y
                             + qa[r].z * kb[c].z + qa[r].w * kb[c].w;
        }

        // mask + online softmax (row owned by 16 tx-lanes of same half-warp)
#pragma unroll
        for (int r = 0; r < 4; r++) {
            int iq = q0 + ty * 4 + r;
#pragma unroll
            for (int c = 0; c < 4; c++) {
                int jg = j0 + tx * 4 + c;
                if (jg > iq) s[r][c] = NEG_INF;
            }
            float mr = fmaxf(fmaxf(s[r][0], s[r][1]), fmaxf(s[r][2], s[r][3]));
            mr = fmaxf(mr, __shfl_xor_sync(0xffffffffu, mr, 1));
            mr = fmaxf(mr, __shfl_xor_sync(0xffffffffu, mr, 2));
            mr = fmaxf(mr, __shfl_xor_sync(0xffffffffu, mr, 4));
            mr = fmaxf(mr, __shfl_xor_sync(0xffffffffu, mr, 8));
            float mn = fmaxf(m[r], mr);
            float alpha = __expf(m[r] - mn);
            m[r] = mn;
            float rs = 0.f;
#pragma unroll
            for (int c = 0; c < 4; c++) {
                float p = __expf(s[r][c] - mn);
                s[r][c] = p;
                rs += p;
            }
            rs += __shfl_xor_sync(0xffffffffu, rs, 1);
            rs += __shfl_xor_sync(0xffffffffu, rs, 2);
            rs += __shfl_xor_sync(0xffffffffu, rs, 4);
            rs += __shfl_xor_sync(0xffffffffu, rs, 8);
            l[r] = l[r] * alpha + rs;
#pragma unroll
            for (int c = 0; c < 8; c++) o[r][c] *= alpha;
            *(float4*)&p_s[(ty * 4 + r) * 68 + tx * 4] =
                make_float4(s[r][0], s[r][1], s[r][2], s[r][3]);
        }
        __syncthreads();

        // O += P @ V
#pragma unroll 8
        for (int kk = 0; kk < 64; kk++) {
            int sw = kk >> 2;
            float4 v0 = *(const float4*)&v_s[kk * 128 + (((tx << 1) ^ sw) << 2)];
            float4 v1 = *(const float4*)&v_s[kk * 128 + ((((tx << 1) | 1) ^ sw) << 2)];
            float p0 = p_s[(ty * 4 + 0) * 68 + kk];
            float p1 = p_s[(ty * 4 + 1) * 68 + kk];
            float p2 = p_s[(ty * 4 + 2) * 68 + kk];
            float p3 = p_s[(ty * 4 + 3) * 68 + kk];
            float pr[4] = {p0, p1, p2, p3};
#pragma unroll
            for (int r = 0; r < 4; r++) {
                o[r][0] += pr[r] * v0.x;  o[r][1] += pr[r] * v0.y;
                o[r][2] += pr[r] * v0.z;  o[r][3] += pr[r] * v0.w;
                o[r][4] += pr[r] * v1.x;  o[r][5] += pr[r] * v1.y;
                o[r][6] += pr[r] * v1.z;  o[r][7] += pr[r] * v1.w;
            }
        }
    }

    // normalize + store  (cols tx*8 .. tx*8+7)
#pragma unroll
    for (int r = 0; r < 4; r++) {
        float il = 1.0f / l[r];
        size_t rowg = (size_t)(b * T_SEQ + q0 + ty * 4 + r);
        float* op = gout + rowg * DMODEL + h * DH + tx * 8;
        *(float4*)op       = make_float4(o[r][0] * il, o[r][1] * il, o[r][2] * il, o[r][3] * il);
        *(float4*)(op + 4) = make_float4(o[r][4] * il, o[r][5] * il, o[r][6] * il, o[r][7] * il);
    }
}

// ---------------- launch ----------------
extern "C" void kernel_launch(void* const* d_in, const int* in_sizes, int n_in,
                              void* d_out, int out_size) {
    const float* x  = (const float*)d_in[0];
    const float* Wq = (const float*)d_in[1];
    const float* Wk = (const float*)d_in[2];
    const float* Wv = (const float*)d_in[3];
    const float* Wo = (const float*)d_in[4];
    float* out = (float*)d_out;

    float *q, *k, *v, *ao;
    cudaGetSymbolAddress((void**)&q,  g_q);
    cudaGetSymbolAddress((void**)&k,  g_k);
    cudaGetSymbolAddress((void**)&v,  g_v);
    cudaGetSymbolAddress((void**)&ao, g_ao);

    cudaFuncSetAttribute(attn_kernel, cudaFuncAttributeMaxDynamicSharedMemorySize, ATT_SMEM);

    rope_table_kernel<<<512, 256>>>();
    sgemm_kernel<<<dim3(16, 32), 256>>>(x,  Wq, q,   DMODEL,    1);  // Q + RoPE
    sgemm_kernel<<<dim3( 4, 32), 256>>>(x,  Wk, k,   NKV * DH,  1);  // K + RoPE
    sgemm_kernel<<<dim3( 4, 32), 256>>>(x,  Wv, v,   NKV * DH,  0);  // V
    attn_kernel <<<dim3(32, NH, BATCH), 256, ATT_SMEM>>>(q, k, v, ao);
    sgemm_kernel<<<dim3(16, 32), 256>>>(ao, Wo, out, DMODEL,    0);  // out proj
}

// round 3
// speedup vs baseline: 1.6228x; 1.6228x over previous
#include <cuda_runtime.h>
#include <cuda_bf16.h>
#include <math.h>
#include <stdint.h>

// ---------------- problem constants ----------------
#define T_SEQ   2048
#define DMODEL  2048
#define NH      16
#define NKV     4
#define DH      128
#define BATCH   2
#define NROWS   (BATCH * T_SEQ)   // 4096
#define KDIM    2048
#define KC      64                // K chunk (64 bf16 = 128B rows -> SW128 atom)
#define NCHUNK  (KDIM / KC)       // 32

typedef __nv_bfloat16 bf16;

// ---------------- scratch (device globals; no runtime alloc) ----------------
__device__ float g_q [(size_t)NROWS * DMODEL];
__device__ float g_k [(size_t)NROWS * (NKV * DH)];
__device__ float g_v [(size_t)NROWS * (NKV * DH)];
__device__ float g_ao[(size_t)NROWS * DMODEL];
__device__ float g_rc[T_SEQ * 64];
__device__ float g_rs[T_SEQ * 64];

__device__ bf16 g_xhi [(size_t)NROWS * KDIM];
__device__ bf16 g_xlo [(size_t)NROWS * KDIM];
__device__ bf16 g_aohi[(size_t)NROWS * KDIM];
__device__ bf16 g_aolo[(size_t)NROWS * KDIM];
__device__ bf16 g_wqth[(size_t)2048 * KDIM];
__device__ bf16 g_wqtl[(size_t)2048 * KDIM];
__device__ bf16 g_wkth[(size_t)512  * KDIM];
__device__ bf16 g_wktl[(size_t)512  * KDIM];
__device__ bf16 g_wvth[(size_t)512  * KDIM];
__device__ bf16 g_wvtl[(size_t)512  * KDIM];
__device__ bf16 g_woth[(size_t)2048 * KDIM];
__device__ bf16 g_wotl[(size_t)2048 * KDIM];

// ---------------- PTX helpers ----------------
__device__ __forceinline__ uint32_t smem_u32(const void* p) {
    uint32_t a;
    asm("{ .reg .u64 t; cvta.to.shared.u64 t, %1; cvt.u32.u64 %0, t; }" : "=r"(a) : "l"(p));
    return a;
}
__device__ __forceinline__ void cp16(uint32_t dst, const void* src) {
    asm volatile("cp.async.cg.shared.global [%0], [%1], 16;" :: "r"(dst), "l"(src));
}
__device__ __forceinline__ void ldm_x4(uint32_t* r, uint32_t addr) {
    asm volatile("ldmatrix.sync.aligned.m8n8.x4.shared.b16 {%0,%1,%2,%3}, [%4];"
                 : "=r"(r[0]), "=r"(r[1]), "=r"(r[2]), "=r"(r[3]) : "r"(addr));
}
__device__ __forceinline__ void mma_bf16(float* d, const uint32_t* a,
                                         uint32_t b0, uint32_t b1) {
    asm volatile(
        "mma.sync.aligned.m16n8k16.row.col.f32.bf16.bf16.f32 "
        "{%0,%1,%2,%3}, {%4,%5,%6,%7}, {%8,%9}, {%0,%1,%2,%3};"
        : "+f"(d[0]), "+f"(d[1]), "+f"(d[2]), "+f"(d[3])
        : "r"(a[0]), "r"(a[1]), "r"(a[2]), "r"(a[3]), "r"(b0), "r"(b1));
}

// ---------------- RoPE table ----------------
__global__ void rope_table_kernel() {
    int idx = blockIdx.x * 256 + threadIdx.x;
    if (idx >= T_SEQ * 64) return;
    int t = idx >> 6;
    int j = idx & 63;
    double inv = pow(10000.0, -(double)j / 64.0);
    double f   = (double)t * inv;
    g_rc[idx] = (float)cos(f);
    g_rs[idx] = (float)sin(f);
}

// ---------------- fp32 -> (hi, lo) bf16 split, elementwise ----------------
__global__ void conv_split_kernel(const float* __restrict__ src,
                                  bf16* __restrict__ hi, bf16* __restrict__ lo) {
    int i = blockIdx.x * 256 + threadIdx.x;      // one float4 per thread
    float4 v = ((const float4*)src)[i];
    bf16 h0 = __float2bfloat16_rn(v.x), h1 = __float2bfloat16_rn(v.y);
    bf16 h2 = __float2bfloat16_rn(v.z), h3 = __float2bfloat16_rn(v.w);
    bf16 l0 = __float2bfloat16_rn(v.x - __bfloat162float(h0));
    bf16 l1 = __float2bfloat16_rn(v.y - __bfloat162float(h1));
    bf16 l2 = __float2bfloat16_rn(v.z - __bfloat162float(h2));
    bf16 l3 = __float2bfloat16_rn(v.w - __bfloat162float(h3));
    __nv_bfloat162* hp = (__nv_bfloat162*)(hi + (size_t)i * 4);
    __nv_bfloat162* lp = (__nv_bfloat162*)(lo + (size_t)i * 4);
    hp[0] = __nv_bfloat162(h0, h1);  hp[1] = __nv_bfloat162(h2, h3);
    lp[0] = __nv_bfloat162(l0, l1);  lp[1] = __nv_bfloat162(l2, l3);
}

// ---------------- W [K=2048, N] -> Wt hi/lo [N, K] bf16 (tiled transpose) ----------------
__global__ void wtrans_kernel(const float* __restrict__ W,
                              bf16* __restrict__ Thi, bf16* __restrict__ Tlo, int N) {
    __shared__ float t[32][33];
    int n0 = blockIdx.x * 32, k0 = blockIdx.y * 32;
    int tx = threadIdx.x, ty = threadIdx.y;
#pragma unroll
    for (int i = ty; i < 32; i += 8)
        t[i][tx] = W[(size_t)(k0 + i) * N + n0 + tx];
    __syncthreads();
#pragma unroll
    for (int i = ty; i < 32; i += 8) {
        float v = t[tx][i];
        bf16 h = __float2bfloat16_rn(v);
        bf16 l = __float2bfloat16_rn(v - __bfloat162float(h));
        size_t o = (size_t)(n0 + i) * KDIM + k0 + tx;
        Thi[o] = h;
        Tlo[o] = l;
    }
}

// ---------------- HMMA split-bf16 GEMM ----------------
// CTA: 128x128 output, 8 warps (warp tile 32m x 64n), KC=64 chunks,
// double-buffered cp.async, SW128-swizzled smem, ldmatrix + mma.sync,
// fp32 register accumulators, fused RoPE epilogue.
#define GEMM_SMEM (2 * 4 * 16384)     // 131072

__device__ __forceinline__ void prefetch_chunk(
    uint32_t bufb, const bf16* Ahi, const bf16* Alo, const bf16* Bhi, const bf16* Blo,
    int bm, int bn, int kb, int tid) {
    const bf16* srcs[4] = {Ahi, Alo, Bhi, Blo};
#pragma unroll
    for (int s = 0; s < 4; s++) {
        int rb = (s < 2) ? bm : bn;
        const bf16* src = srcs[s];
#pragma unroll
        for (int i = 0; i < 4; i++) {
            int idx = tid + 256 * i;            // 0..1023
            int row = idx >> 3, c16 = idx & 7;
            const void* g = src + (size_t)(rb + row) * KDIM + kb + c16 * 8;
            uint32_t off = row * 128 + c16 * 16;
            off ^= (off >> 3) & 0x70;           // SW128
            cp16(bufb + s * 16384 + off, g);
        }
    }
}

__global__ __launch_bounds__(256, 1)
void tc_gemm(const bf16* __restrict__ Ahi, const bf16* __restrict__ Alo,
             const bf16* __restrict__ Bhi, const bf16* __restrict__ Blo,
             float* __restrict__ C, int ldC, int doRope) {
    extern __shared__ char sm[];
    uint32_t sb = smem_u32(sm);
    const int tid = threadIdx.x;
    const int wid = tid >> 5, lane = tid & 31;
    const int wm = wid & 3, wn = wid >> 2;      // warp grid 4(m) x 2(n)
    const int grp = lane >> 2, tig = lane & 3;
    const int bn = blockIdx.x * 128;
    const int bm = blockIdx.y * 128;

    float acc[2][8][4];
#pragma unroll
    for (int i = 0; i < 2; i++)
#pragma unroll
        for (int j = 0; j < 8; j++)
#pragma unroll
            for (int q = 0; q < 4; q++) acc[i][j][q] = 0.f;

    // ldmatrix row/col-in-tile for this lane (lanes 0-15: rows 0-15 @ +0B,
    // lanes 16-31: rows 0-15 @ +16B)
    const int lrow = lane & 15;
    const int lcb  = ((lane >> 4) & 1) * 16;

    prefetch_chunk(sb, Ahi, Alo, Bhi, Blo, bm, bn, 0, tid);
    asm volatile("cp.async.commit_group;");

    for (int c = 0; c < NCHUNK; c++) {
        asm volatile("cp.async.wait_group 0;");
        __syncthreads();
        if (c + 1 < NCHUNK) {
            prefetch_chunk(sb + ((c + 1) & 1) * 65536,
                           Ahi, Alo, Bhi, Blo, bm, bn, (c + 1) * KC, tid);
            asm volatile("cp.async.commit_group;");
        }

        uint32_t tb = sb + (c & 1) * 65536;
#pragma unroll
        for (int ka = 0; ka < 4; ka++) {
            int kcb = ka * 32 + lcb;            // byte col of this lane's 16B row chunk
            // A fragments (hi & lo) for 2 m-atoms
            uint32_t ah[2][4], al[2][4];
#pragma unroll
            for (int i = 0; i < 2; i++) {
                int row = wm * 32 + i * 16 + lrow;
                uint32_t off = row * 128 + kcb;
                off ^= (off >> 3) & 0x70;
                ldm_x4(ah[i], tb + off);
                ldm_x4(al[i], tb + 16384 + off);
            }
#pragma unroll
            for (int jg = 0; jg < 4; jg++) {    // B groups of 2 n-atoms
                int row = wn * 64 + jg * 16 + lrow;
                uint32_t off = row * 128 + kcb;
                off ^= (off >> 3) & 0x70;
                uint32_t bh[4], bl[4];
                ldm_x4(bh, tb + 32768 + off);
                ldm_x4(bl, tb + 49152 + off);
#pragma unroll
                for (int jo = 0; jo < 2; jo++) {
                    int j = jg * 2 + jo;
#pragma unroll
                    for (int i = 0; i < 2; i++) {
                        mma_bf16(acc[i][j], ah[i], bh[jo], bh[jo + 2]);  // hi*hi
                        mma_bf16(acc[i][j], ah[i], bl[jo], bl[jo + 2]);  // hi*lo
                        mma_bf16(acc[i][j], al[i], bh[jo], bh[jo + 2]);  // lo*hi
                    }
                }
            }
        }
        __syncthreads();   // compute done before next buffer overwrite cycle
    }

    // epilogue: optional RoPE on (even,odd) pairs (both live in c0,c1 / c2,c3)
#pragma unroll
    for (int i = 0; i < 2; i++) {
#pragma unroll
        for (int j = 0; j < 8; j++) {
            int row0 = bm + wm * 32 + i * 16 + grp;
            int row1 = row0 + 8;
            int col  = bn + wn * 64 + j * 8 + tig * 2;
            float c0 = acc[i][j][0], c1 = acc[i][j][1];
            float c2 = acc[i][j][2], c3 = acc[i][j][3];
            if (doRope) {
                int jj = (col & 127) >> 1;
                int t0 = row0 & (T_SEQ - 1);
                int t1 = row1 & (T_SEQ - 1);
                float ct0 = g_rc[(t0 << 6) + jj], st0 = g_rs[(t0 << 6) + jj];
                float ct1 = g_rc[(t1 << 6) + jj], st1 = g_rs[(t1 << 6) + jj];
                float e0 = c0, o0 = c1, e1 = c2, o1 = c3;
                c0 = e0 * ct0 - o0 * st0;  c1 = e0 * st0 + o0 * ct0;
                c2 = e1 * ct1 - o1 * st1;  c3 = e1 * st1 + o1 * ct1;
            }
            *(float2*)(C + (size_t)row0 * ldC + col) = make_float2(c0, c1);
            *(float2*)(C + (size_t)row1 * ldC + col) = make_float2(c2, c3);
        }
    }
}

// ---------------- Flash attention (unchanged) ----------------
#define ATT_SMEM ((3 * 64 * 128 + 64 * 68) * 4)

__global__ __launch_bounds__(256, 1)
void attn_kernel(const float* __restrict__ gq, const float* __restrict__ gk,
                 const float* __restrict__ gv, float* __restrict__ gout) {
    extern __shared__ float smf[];
    float* q_s = smf;
    float* k_s = q_s + 64 * 128;
    float* v_s = k_s + 64 * 128;
    float* p_s = v_s + 64 * 128;

    int tid = threadIdx.x;
    int tx = tid & 15, ty = tid >> 4;
    int qt = blockIdx.x, h = blockIdx.y, b = blockIdx.z;
    int q0 = qt * 64;
    int kvh = h >> 2;
    const float scale = 0.08838834764831845f;
    const float NEG_INF = __int_as_float(0xff800000);

    {
        const float* qbase = gq + ((size_t)(b * T_SEQ + q0)) * DMODEL + h * DH;
#pragma unroll
        for (int i = 0; i < 8; i++) {
            int idx = tid + 256 * i;
            int row = idx >> 5;
            int c4  = idx & 31;
            float4 vq = *(const float4*)(qbase + (size_t)row * DMODEL + c4 * 4);
            vq.x *= scale; vq.y *= scale; vq.z *= scale; vq.w *= scale;
            int sc4 = c4 ^ (row >> 2);
            *(float4*)&q_s[row * 128 + sc4 * 4] = vq;
        }
    }

    float m[4], l[4], o[4][8];
#pragma unroll
    for (int r = 0; r < 4; r++) {
        m[r] = NEG_INF; l[r] = 0.f;
#pragma unroll
        for (int c = 0; c < 8; c++) o[r][c] = 0.f;
    }

    int ntiles = (qt + 1 < 18) ? (qt + 1) : 18;
    for (int jt = 0; jt < ntiles; jt++) {
        int j0 = jt * 64;
        __syncthreads();
#pragma unroll
        for (int i = 0; i < 8; i++) {
            int idx = tid + 256 * i;
            int row = idx >> 5;
            int c4  = idx & 31;
            int jg = j0 + row;
            int kpos = (jg < 128) ? jg : (jg + 896);
            size_t base = ((size_t)(b * T_SEQ + kpos)) * (NKV * DH) + kvh * DH + c4 * 4;
            int sc4 = c4 ^ (row >> 2);
            *(float4*)&k_s[row * 128 + sc4 * 4] = *(const float4*)(gk + base);
            *(float4*)&v_s[row * 128 + sc4 * 4] = *(const float4*)(gv + base);
        }
        __syncthreads();

        float s[4][4];
#pragma unroll
        for (int r = 0; r < 4; r++)
#pragma unroll
            for (int c = 0; c < 4; c++) s[r][c] = 0.f;

#pragma unroll 8
        for (int kk4 = 0; kk4 < 32; kk4++) {
            float4 qa[4], kb[4];
#pragma unroll
            for (int r = 0; r < 4; r++)
                qa[r] = *(const float4*)&q_s[(ty * 4 + r) * 128 + ((kk4 ^ ty) << 2)];
#pragma unroll
            for (int c = 0; c < 4; c++)
                kb[c] = *(const float4*)&k_s[(tx * 4 + c) * 128 + ((kk4 ^ tx) << 2)];
#pragma unroll
            for (int r = 0; r < 4; r++)
#pragma unroll
                for (int c = 0; c < 4; c++)
                    s[r][c] += qa[r].x * kb[c].x + qa[r].y * kb[c].y
                             + qa[r].z * kb[c].z + qa[r].w * kb[c].w;
        }

#pragma unroll
        for (int r = 0; r < 4; r++) {
            int iq = q0 + ty * 4 + r;
#pragma unroll
            for (int c = 0; c < 4; c++) {
                int jg = j0 + tx * 4 + c;
                if (jg > iq) s[r][c] = NEG_INF;
            }
            float mr = fmaxf(fmaxf(s[r][0], s[r][1]), fmaxf(s[r][2], s[r][3]));
            mr = fmaxf(mr, __shfl_xor_sync(0xffffffffu, mr, 1));
            mr = fmaxf(mr, __shfl_xor_sync(0xffffffffu, mr, 2));
            mr = fmaxf(mr, __shfl_xor_sync(0xffffffffu, mr, 4));
            mr = fmaxf(mr, __shfl_xor_sync(0xffffffffu, mr, 8));
            float mn = fmaxf(m[r], mr);
            float alpha = __expf(m[r] - mn);
            m[r] = mn;
            float rs = 0.f;
#pragma unroll
            for (int c = 0; c < 4; c++) {
                float p = __expf(s[r][c] - mn);
                s[r][c] = p;
                rs += p;
            }
            rs += __shfl_xor_sync(0xffffffffu, rs, 1);
            rs += __shfl_xor_sync(0xffffffffu, rs, 2);
            rs += __shfl_xor_sync(0xffffffffu, rs, 4);
            rs += __shfl_xor_sync(0xffffffffu, rs, 8);
            l[r] = l[r] * alpha + rs;
#pragma unroll
            for (int c = 0; c < 8; c++) o[r][c] *= alpha;
            *(float4*)&p_s[(ty * 4 + r) * 68 + tx * 4] =
                make_float4(s[r][0], s[r][1], s[r][2], s[r][3]);
        }
        __syncthreads();

#pragma unroll 8
        for (int kk = 0; kk < 64; kk++) {
            int sw = kk >> 2;
            float4 v0 = *(const float4*)&v_s[kk * 128 + (((tx << 1) ^ sw) << 2)];
            float4 v1 = *(const float4*)&v_s[kk * 128 + ((((tx << 1) | 1) ^ sw) << 2)];
            float p0 = p_s[(ty * 4 + 0) * 68 + kk];
            float p1 = p_s[(ty * 4 + 1) * 68 + kk];
            float p2 = p_s[(ty * 4 + 2) * 68 + kk];
            float p3 = p_s[(ty * 4 + 3) * 68 + kk];
            float pr[4] = {p0, p1, p2, p3};
#pragma unroll
            for (int r = 0; r < 4; r++) {
                o[r][0] += pr[r] * v0.x;  o[r][1] += pr[r] * v0.y;
                o[r][2] += pr[r] * v0.z;  o[r][3] += pr[r] * v0.w;
                o[r][4] += pr[r] * v1.x;  o[r][5] += pr[r] * v1.y;
                o[r][6] += pr[r] * v1.z;  o[r][7] += pr[r] * v1.w;
            }
        }
    }

#pragma unroll
    for (int r = 0; r < 4; r++) {
        float il = 1.0f / l[r];
        size_t rowg = (size_t)(b * T_SEQ + q0 + ty * 4 + r);
        float* op = gout + rowg * DMODEL + h * DH + tx * 8;
        *(float4*)op       = make_float4(o[r][0] * il, o[r][1] * il, o[r][2] * il, o[r][3] * il);
        *(float4*)(op + 4) = make_float4(o[r][4] * il, o[r][5] * il, o[r][6] * il, o[r][7] * il);
    }
}

// ---------------- launch ----------------
extern "C" void kernel_launch(void* const* d_in, const int* in_sizes, int n_in,
                              void* d_out, int out_size) {
    const float* x  = (const float*)d_in[0];
    const float* Wq = (const float*)d_in[1];
    const float* Wk = (const float*)d_in[2];
    const float* Wv = (const float*)d_in[3];
    const float* Wo = (const float*)d_in[4];
    float* out = (float*)d_out;

    float *q, *k, *v, *ao;
    bf16 *xhi, *xlo, *aohi, *aolo;
    bf16 *wqth, *wqtl, *wkth, *wktl, *wvth, *wvtl, *woth, *wotl;
    cudaGetSymbolAddress((void**)&q,    g_q);
    cudaGetSymbolAddress((void**)&k,    g_k);
    cudaGetSymbolAddress((void**)&v,    g_v);
    cudaGetSymbolAddress((void**)&ao,   g_ao);
    cudaGetSymbolAddress((void**)&xhi,  g_xhi);
    cudaGetSymbolAddress((void**)&xlo,  g_xlo);
    cudaGetSymbolAddress((void**)&aohi, g_aohi);
    cudaGetSymbolAddress((void**)&aolo, g_aolo);
    cudaGetSymbolAddress((void**)&wqth, g_wqth);
    cudaGetSymbolAddress((void**)&wqtl, g_wqtl);
    cudaGetSymbolAddress((void**)&wkth, g_wkth);
    cudaGetSymbolAddress((void**)&wktl, g_wktl);
    cudaGetSymbolAddress((void**)&wvth, g_wvth);
    cudaGetSymbolAddress((void**)&wvtl, g_wvtl);
    cudaGetSymbolAddress((void**)&woth, g_woth);
    cudaGetSymbolAddress((void**)&wotl, g_wotl);

    cudaFuncSetAttribute(tc_gemm,     cudaFuncAttributeMaxDynamicSharedMemorySize, GEMM_SMEM);
    cudaFuncSetAttribute(attn_kernel, cudaFuncAttributeMaxDynamicSharedMemorySize, ATT_SMEM);

    rope_table_kernel<<<512, 256>>>();
    conv_split_kernel<<<8192, 256>>>(x, xhi, xlo);
    wtrans_kernel<<<dim3(64, 64), dim3(32, 8)>>>(Wq, wqth, wqtl, 2048);
    wtrans_kernel<<<dim3(16, 64), dim3(32, 8)>>>(Wk, wkth, wktl, 512);
    wtrans_kernel<<<dim3(16, 64), dim3(32, 8)>>>(Wv, wvth, wvtl, 512);
    wtrans_kernel<<<dim3(64, 64), dim3(32, 8)>>>(Wo, woth, wotl, 2048);

    tc_gemm<<<dim3(16, 32), 256, GEMM_SMEM>>>(xhi, xlo, wqth, wqtl, q, DMODEL, 1);
    tc_gemm<<<dim3( 4, 32), 256, GEMM_SMEM>>>(xhi, xlo, wkth, wktl, k, NKV * DH, 1);
    tc_gemm<<<dim3( 4, 32), 256, GEMM_SMEM>>>(xhi, xlo, wvth, wvtl, v, NKV * DH, 0);

    attn_kernel<<<dim3(32, NH, BATCH), 256, ATT_SMEM>>>(q, k, v, ao);

    conv_split_kernel<<<8192, 256>>>(ao, aohi, aolo);
    tc_gemm<<<dim3(16, 32), 256, GEMM_SMEM>>>(aohi, aolo, woth, wotl, out, DMODEL, 0);
}

// round 4
// speedup vs baseline: 2.7914x; 1.7201x over previous
#include <cuda_runtime.h>
#include <cuda_bf16.h>
#include <math.h>
#include <stdint.h>

// ---------------- problem constants ----------------
#define T_SEQ   2048
#define DMODEL  2048
#define NH      16
#define NKV     4
#define DH      128
#define BATCH   2
#define NROWS   (BATCH * T_SEQ)   // 4096
#define KDIM    2048
#define KC      64
#define NCHUNK  (KDIM / KC)       // 32

typedef __nv_bfloat16 bf16;

// ---------------- scratch (device globals; no runtime alloc) ----------------
__device__ float g_rc[T_SEQ * 64];
__device__ float g_rs[T_SEQ * 64];

__device__ bf16 g_xhi [(size_t)NROWS * KDIM];
__device__ bf16 g_xlo [(size_t)NROWS * KDIM];
__device__ bf16 g_qhi [(size_t)NROWS * DMODEL];
__device__ bf16 g_qlo [(size_t)NROWS * DMODEL];
__device__ bf16 g_khi [(size_t)NROWS * (NKV * DH)];
__device__ bf16 g_klo [(size_t)NROWS * (NKV * DH)];
__device__ bf16 g_vhi [(size_t)NROWS * (NKV * DH)];
__device__ bf16 g_vlo [(size_t)NROWS * (NKV * DH)];
__device__ bf16 g_aohi[(size_t)NROWS * KDIM];
__device__ bf16 g_aolo[(size_t)NROWS * KDIM];
__device__ bf16 g_wqth[(size_t)2048 * KDIM];
__device__ bf16 g_wqtl[(size_t)2048 * KDIM];
__device__ bf16 g_wkth[(size_t)512  * KDIM];
__device__ bf16 g_wktl[(size_t)512  * KDIM];
__device__ bf16 g_wvth[(size_t)512  * KDIM];
__device__ bf16 g_wvtl[(size_t)512  * KDIM];
__device__ bf16 g_woth[(size_t)2048 * KDIM];
__device__ bf16 g_wotl[(size_t)2048 * KDIM];

// ---------------- PTX helpers ----------------
__device__ __forceinline__ uint32_t smem_u32(const void* p) {
    uint32_t a;
    asm("{ .reg .u64 t; cvta.to.shared.u64 t, %1; cvt.u32.u64 %0, t; }" : "=r"(a) : "l"(p));
    return a;
}
__device__ __forceinline__ void cp16(uint32_t dst, const void* src) {
    asm volatile("cp.async.cg.shared.global [%0], [%1], 16;" :: "r"(dst), "l"(src));
}
__device__ __forceinline__ void ldm_x4(uint32_t* r, uint32_t addr) {
    asm volatile("ldmatrix.sync.aligned.m8n8.x4.shared.b16 {%0,%1,%2,%3}, [%4];"
                 : "=r"(r[0]), "=r"(r[1]), "=r"(r[2]), "=r"(r[3]) : "r"(addr));
}
__device__ __forceinline__ void ldm_x4t(uint32_t* r, uint32_t addr) {
    asm volatile("ldmatrix.sync.aligned.m8n8.x4.trans.shared.b16 {%0,%1,%2,%3}, [%4];"
                 : "=r"(r[0]), "=r"(r[1]), "=r"(r[2]), "=r"(r[3]) : "r"(addr));
}
__device__ __forceinline__ void mma_bf16(float* d, const uint32_t* a,
                                         uint32_t b0, uint32_t b1) {
    asm volatile(
        "mma.sync.aligned.m16n8k16.row.col.f32.bf16.bf16.f32 "
        "{%0,%1,%2,%3}, {%4,%5,%6,%7}, {%8,%9}, {%0,%1,%2,%3};"
        : "+f"(d[0]), "+f"(d[1]), "+f"(d[2]), "+f"(d[3])
        : "r"(a[0]), "r"(a[1]), "r"(a[2]), "r"(a[3]), "r"(b0), "r"(b1));
}
__device__ __forceinline__ uint32_t packbf(float a, float b) {
    uint32_t lo = (uint32_t)__bfloat16_as_ushort(__float2bfloat16_rn(a));
    uint32_t hi = (uint32_t)__bfloat16_as_ushort(__float2bfloat16_rn(b));
    return lo | (hi << 16);
}
// swizzled byte offset for 256B-row tiles: chunk c (16B) of row r
__device__ __forceinline__ uint32_t swz256(int row, int c) {
    return (uint32_t)(row * 256 + ((c ^ (row & 7)) << 4));
}

// ---------------- RoPE table ----------------
__global__ void rope_table_kernel() {
    int idx = blockIdx.x * 256 + threadIdx.x;
    if (idx >= T_SEQ * 64) return;
    int t = idx >> 6;
    int j = idx & 63;
    double inv = pow(10000.0, -(double)j / 64.0);
    double f   = (double)t * inv;
    g_rc[idx] = (float)cos(f);
    g_rs[idx] = (float)sin(f);
}

// ---------------- fp32 -> (hi, lo) bf16 split ----------------
__global__ void conv_split_kernel(const float* __restrict__ src,
                                  bf16* __restrict__ hi, bf16* __restrict__ lo) {
    int i = blockIdx.x * 256 + threadIdx.x;
    float4 v = ((const float4*)src)[i];
    bf16 h0 = __float2bfloat16_rn(v.x), h1 = __float2bfloat16_rn(v.y);
    bf16 h2 = __float2bfloat16_rn(v.z), h3 = __float2bfloat16_rn(v.w);
    bf16 l0 = __float2bfloat16_rn(v.x - __bfloat162float(h0));
    bf16 l1 = __float2bfloat16_rn(v.y - __bfloat162float(h1));
    bf16 l2 = __float2bfloat16_rn(v.z - __bfloat162float(h2));
    bf16 l3 = __float2bfloat16_rn(v.w - __bfloat162float(h3));
    __nv_bfloat162* hp = (__nv_bfloat162*)(hi + (size_t)i * 4);
    __nv_bfloat162* lp = (__nv_bfloat162*)(lo + (size_t)i * 4);
    hp[0] = __nv_bfloat162(h0, h1);  hp[1] = __nv_bfloat162(h2, h3);
    lp[0] = __nv_bfloat162(l0, l1);  lp[1] = __nv_bfloat162(l2, l3);
}

// ---------------- W transpose + split ----------------
__global__ void wtrans_kernel(const float* __restrict__ W,
                              bf16* __restrict__ Thi, bf16* __restrict__ Tlo, int N) {
    __shared__ float t[32][33];
    int n0 = blockIdx.x * 32, k0 = blockIdx.y * 32;
    int tx = threadIdx.x, ty = threadIdx.y;
#pragma unroll
    for (int i = ty; i < 32; i += 8)
        t[i][tx] = W[(size_t)(k0 + i) * N + n0 + tx];
    __syncthreads();
#pragma unroll
    for (int i = ty; i < 32; i += 8) {
        float v = t[tx][i];
        bf16 h = __float2bfloat16_rn(v);
        bf16 l = __float2bfloat16_rn(v - __bfloat162float(h));
        size_t o = (size_t)(n0 + i) * KDIM + k0 + tx;
        Thi[o] = h;
        Tlo[o] = l;
    }
}

// ---------------- HMMA split-bf16 GEMM ----------------
#define GEMM_SMEM (2 * 4 * 16384)     // 131072

__device__ __forceinline__ void prefetch_chunk(
    uint32_t bufb, const bf16* Ahi, const bf16* Alo, const bf16* Bhi, const bf16* Blo,
    int bm, int bn, int kb, int tid) {
    const bf16* srcs[4] = {Ahi, Alo, Bhi, Blo};
#pragma unroll
    for (int s = 0; s < 4; s++) {
        int rb = (s < 2) ? bm : bn;
        const bf16* src = srcs[s];
#pragma unroll
        for (int i = 0; i < 4; i++) {
            int idx = tid + 256 * i;
            int row = idx >> 3, c16 = idx & 7;
            const void* g = src + (size_t)(rb + row) * KDIM + kb + c16 * 8;
            uint32_t off = row * 128 + c16 * 16;
            off ^= (off >> 3) & 0x70;           // SW128 (128B rows)
            cp16(bufb + s * 16384 + off, g);
        }
    }
}

__global__ __launch_bounds__(256, 1)
void tc_gemm(const bf16* __restrict__ Ahi, const bf16* __restrict__ Alo,
             const bf16* __restrict__ Bhi, const bf16* __restrict__ Blo,
             float* __restrict__ C, bf16* __restrict__ Chi, bf16* __restrict__ Clo,
             int ldC, int doRope) {
    extern __shared__ char sm[];
    uint32_t sb = smem_u32(sm);
    const int tid = threadIdx.x;
    const int wid = tid >> 5, lane = tid & 31;
    const int wm = wid & 3, wn = wid >> 2;
    const int grp = lane >> 2, tig = lane & 3;
    const int bn = blockIdx.x * 128;
    const int bm = blockIdx.y * 128;

    float acc[2][8][4];
#pragma unroll
    for (int i = 0; i < 2; i++)
#pragma unroll
        for (int j = 0; j < 8; j++)
#pragma unroll
            for (int q = 0; q < 4; q++) acc[i][j][q] = 0.f;

    const int lrow = lane & 15;
    const int lcb  = ((lane >> 4) & 1) * 16;

    prefetch_chunk(sb, Ahi, Alo, Bhi, Blo, bm, bn, 0, tid);
    asm volatile("cp.async.commit_group;");

    for (int c = 0; c < NCHUNK; c++) {
        asm volatile("cp.async.wait_group 0;");
        __syncthreads();
        if (c + 1 < NCHUNK) {
            prefetch_chunk(sb + ((c + 1) & 1) * 65536,
                           Ahi, Alo, Bhi, Blo, bm, bn, (c + 1) * KC, tid);
            asm volatile("cp.async.commit_group;");
        }

        uint32_t tb = sb + (c & 1) * 65536;
#pragma unroll
        for (int ka = 0; ka < 4; ka++) {
            int kcb = ka * 32 + lcb;
            uint32_t ah[2][4], al[2][4];
#pragma unroll
            for (int i = 0; i < 2; i++) {
                int row = wm * 32 + i * 16 + lrow;
                uint32_t off = row * 128 + kcb;
                off ^= (off >> 3) & 0x70;
                ldm_x4(ah[i], tb + off);
                ldm_x4(al[i], tb + 16384 + off);
            }
#pragma unroll
            for (int jg = 0; jg < 4; jg++) {
                int row = wn * 64 + jg * 16 + lrow;
                uint32_t off = row * 128 + kcb;
                off ^= (off >> 3) & 0x70;
                uint32_t bh[4], bl[4];
                ldm_x4(bh, tb + 32768 + off);
                ldm_x4(bl, tb + 49152 + off);
#pragma unroll
                for (int jo = 0; jo < 2; jo++) {
                    int j = jg * 2 + jo;
#pragma unroll
                    for (int i = 0; i < 2; i++) {
                        mma_bf16(acc[i][j], ah[i], bh[jo], bh[jo + 2]);
                        mma_bf16(acc[i][j], ah[i], bl[jo], bl[jo + 2]);
                        mma_bf16(acc[i][j], al[i], bh[jo], bh[jo + 2]);
                    }
                }
            }
        }
        __syncthreads();
    }

#pragma unroll
    for (int i = 0; i < 2; i++) {
#pragma unroll
        for (int j = 0; j < 8; j++) {
            int row0 = bm + wm * 32 + i * 16 + grp;
            int row1 = row0 + 8;
            int col  = bn + wn * 64 + j * 8 + tig * 2;
            float c0 = acc[i][j][0], c1 = acc[i][j][1];
            float c2 = acc[i][j][2], c3 = acc[i][j][3];
            if (doRope) {
                int jj = (col & 127) >> 1;
                int t0 = row0 & (T_SEQ - 1);
                int t1 = row1 & (T_SEQ - 1);
                float ct0 = g_rc[(t0 << 6) + jj], st0 = g_rs[(t0 << 6) + jj];
                float ct1 = g_rc[(t1 << 6) + jj], st1 = g_rs[(t1 << 6) + jj];
                float e0 = c0, o0 = c1, e1 = c2, o1 = c3;
                c0 = e0 * ct0 - o0 * st0;  c1 = e0 * st0 + o0 * ct0;
                c2 = e1 * ct1 - o1 * st1;  c3 = e1 * st1 + o1 * ct1;
            }
            if (Chi) {
                bf16 h0 = __float2bfloat16_rn(c0), h1 = __float2bfloat16_rn(c1);
                bf16 h2 = __float2bfloat16_rn(c2), h3 = __float2bfloat16_rn(c3);
                bf16 l0 = __float2bfloat16_rn(c0 - __bfloat162float(h0));
                bf16 l1 = __float2bfloat16_rn(c1 - __bfloat162float(h1));
                bf16 l2 = __float2bfloat16_rn(c2 - __bfloat162float(h2));
                bf16 l3 = __float2bfloat16_rn(c3 - __bfloat162float(h3));
                *(__nv_bfloat162*)(Chi + (size_t)row0 * ldC + col) = __nv_bfloat162(h0, h1);
                *(__nv_bfloat162*)(Chi + (size_t)row1 * ldC + col) = __nv_bfloat162(h2, h3);
                *(__nv_bfloat162*)(Clo + (size_t)row0 * ldC + col) = __nv_bfloat162(l0, l1);
                *(__nv_bfloat162*)(Clo + (size_t)row1 * ldC + col) = __nv_bfloat162(l2, l3);
            } else {
                *(float2*)(C + (size_t)row0 * ldC + col) = make_float2(c0, c1);
                *(float2*)(C + (size_t)row1 * ldC + col) = make_float2(c2, c3);
            }
        }
    }
}

// ---------------- HMMA flash attention ----------------
// CTA = (128 q-rows, head, batch), 8 warps (m16 each). Key tile = 64,
// double-buffered cp.async K/V stages. Split-bf16 QK^T and PV; fp32 softmax.
// smem: qh 32K, ql 32K, 2 stages x (kh,kl,vh,vl 16K each) = 192KB
#define ATT_SMEM (65536 + 2 * 65536)

__global__ __launch_bounds__(256, 1)
void attn_mma(const bf16* __restrict__ qhi, const bf16* __restrict__ qlo,
              const bf16* __restrict__ khi, const bf16* __restrict__ klo,
              const bf16* __restrict__ vhi, const bf16* __restrict__ vlo,
              bf16* __restrict__ aoh, bf16* __restrict__ aol) {
    extern __shared__ char sm[];
    uint32_t sb = smem_u32(sm);
    const int tid = threadIdx.x, w = tid >> 5, lane = tid & 31;
    const int grp = lane >> 2, tig = lane & 3;
    const int lrow = lane & 15, lhalf = lane >> 4;
    const int qt = blockIdx.x, h = blockIdx.y, b = blockIdx.z;
    const int q0 = qt * 128, kvh = h >> 2;
    const float scale = 0.08838834764831845f;
    const float NEG_INF = __int_as_float(0xff800000);

    const uint32_t QH = sb, QL = sb + 32768;
    const uint32_t ST = sb + 65536;

    // load Q tile (hi+lo)
#pragma unroll
    for (int i = 0; i < 8; i++) {
        int ck = tid + 256 * i;
        int row = ck >> 4, c = ck & 15;
        uint32_t off = swz256(row, c);
        size_t src = (size_t)(b * T_SEQ + q0 + row) * DMODEL + h * DH + c * 8;
        cp16(QH + off, qhi + src);
        cp16(QL + off, qlo + src);
    }
    // prefetch KV tile 0
    {
#pragma unroll
        for (int i = 0; i < 4; i++) {
            int ck = tid + 256 * i;
            int row = ck >> 4, c = ck & 15;
            uint32_t off = swz256(row, c);
            int jg = row;                         // j0 = 0
            int kpos = jg;                        // jg < 128 always here
            size_t s = (size_t)(b * T_SEQ + kpos) * (NKV * DH) + kvh * DH + c * 8;
            cp16(ST + off,         khi + s);
            cp16(ST + 16384 + off, klo + s);
            cp16(ST + 32768 + off, vhi + s);
            cp16(ST + 49152 + off, vlo + s);
        }
        asm volatile("cp.async.commit_group;");
    }

    float O[16][4];
#pragma unroll
    for (int t = 0; t < 16; t++)
#pragma unroll
        for (int q = 0; q < 4; q++) O[t][q] = 0.f;
    float m0 = NEG_INF, m1 = NEG_INF, l0 = 0.f, l1 = 0.f;

    const int nt = (2 * qt + 2 < 18) ? (2 * qt + 2) : 18;
    const int r0g = q0 + w * 16 + grp;            // this thread's q rows
    const int r1g = r0g + 8;

    for (int jt = 0; jt < nt; jt++) {
        asm volatile("cp.async.wait_group 0;");
        __syncthreads();
        if (jt + 1 < nt) {
            int j0n = (jt + 1) * 64;
            uint32_t dst = ST + ((jt + 1) & 1) * 65536;
#pragma unroll
            for (int i = 0; i < 4; i++) {
                int ck = tid + 256 * i;
                int row = ck >> 4, c = ck & 15;
                uint32_t off = swz256(row, c);
                int jg = j0n + row;
                int kpos = (jg < 128) ? jg : (jg + 896);
                size_t s = (size_t)(b * T_SEQ + kpos) * (NKV * DH) + kvh * DH + c * 8;
                cp16(dst + off,         khi + s);
                cp16(dst + 16384 + off, klo + s);
                cp16(dst + 32768 + off, vhi + s);
                cp16(dst + 49152 + off, vlo + s);
            }
            asm volatile("cp.async.commit_group;");
        }

        const int j0 = jt * 64;
        if (j0 <= q0 + w * 16 + 15) {             // warp has >= 1 unmasked row
            uint32_t tb = ST + (jt & 1) * 65536;
            float S[8][4];
#pragma unroll
            for (int t = 0; t < 8; t++)
#pragma unroll
                for (int q = 0; q < 4; q++) S[t][q] = 0.f;

            // S = Q K^T (3-term split)
#pragma unroll
            for (int kc = 0; kc < 8; kc++) {
                uint32_t qoff = swz256(w * 16 + lrow, kc * 2 + lhalf);
                uint32_t aqh[4], aql[4];
                ldm_x4(aqh, QH + qoff);
                ldm_x4(aql, QL + qoff);
#pragma unroll
                for (int g = 0; g < 4; g++) {
                    uint32_t koff = swz256(g * 16 + lrow, kc * 2 + lhalf);
                    uint32_t bh[4], bl[4];
                    ldm_x4(bh, tb + koff);
                    ldm_x4(bl, tb + 16384 + koff);
                    mma_bf16(S[2*g],   aqh, bh[0], bh[2]);
                    mma_bf16(S[2*g],   aqh, bl[0], bl[2]);
                    mma_bf16(S[2*g],   aql, bh[0], bh[2]);
                    mma_bf16(S[2*g+1], aqh, bh[1], bh[3]);
                    mma_bf16(S[2*g+1], aqh, bl[1], bl[3]);
                    mma_bf16(S[2*g+1], aql, bh[1], bh[3]);
                }
            }

            // scale + mask + online softmax
            float tm0 = NEG_INF, tm1 = NEG_INF;
#pragma unroll
            for (int t = 0; t < 8; t++) {
                int c0 = j0 + 8 * t + 2 * tig, c1 = c0 + 1;
                S[t][0] = (c0 > r0g) ? NEG_INF : S[t][0] * scale;
                S[t][1] = (c1 > r0g) ? NEG_INF : S[t][1] * scale;
                S[t][2] = (c0 > r1g) ? NEG_INF : S[t][2] * scale;
                S[t][3] = (c1 > r1g) ? NEG_INF : S[t][3] * scale;
                tm0 = fmaxf(tm0, fmaxf(S[t][0], S[t][1]));
                tm1 = fmaxf(tm1, fmaxf(S[t][2], S[t][3]));
            }
            tm0 = fmaxf(tm0, __shfl_xor_sync(0xffffffffu, tm0, 1));
            tm0 = fmaxf(tm0, __shfl_xor_sync(0xffffffffu, tm0, 2));
            tm1 = fmaxf(tm1, __shfl_xor_sync(0xffffffffu, tm1, 1));
            tm1 = fmaxf(tm1, __shfl_xor_sync(0xffffffffu, tm1, 2));
            float mn0 = fmaxf(m0, tm0), mn1 = fmaxf(m1, tm1);
            float al0 = __expf(m0 - mn0), al1 = __expf(m1 - mn1);
            m0 = mn0;  m1 = mn1;
            float rs0 = 0.f, rs1 = 0.f;
#pragma unroll
            for (int t = 0; t < 8; t++) {
                S[t][0] = __expf(S[t][0] - mn0);
                S[t][1] = __expf(S[t][1] - mn0);
                S[t][2] = __expf(S[t][2] - mn1);
                S[t][3] = __expf(S[t][3] - mn1);
                rs0 += S[t][0] + S[t][1];
                rs1 += S[t][2] + S[t][3];
            }
            rs0 += __shfl_xor_sync(0xffffffffu, rs0, 1);
            rs0 += __shfl_xor_sync(0xffffffffu, rs0, 2);
            rs1 += __shfl_xor_sync(0xffffffffu, rs1, 1);
            rs1 += __shfl_xor_sync(0xffffffffu, rs1, 2);
            l0 = l0 * al0 + rs0;
            l1 = l1 * al1 + rs1;
#pragma unroll
            for (int t = 0; t < 16; t++) {
                O[t][0] *= al0;  O[t][1] *= al0;
                O[t][2] *= al1;  O[t][3] *= al1;
            }

            // O += P V (3-term split, P from registers)
#pragma unroll
            for (int kk = 0; kk < 4; kk++) {
                uint32_t pha[4], pla[4];
#pragma unroll
                for (int half = 0; half < 2; half++) {
                    int t = 2 * kk + half;
                    float p0 = S[t][0], p1 = S[t][1], p2 = S[t][2], p3 = S[t][3];
                    float h0f = __bfloat162float(__float2bfloat16_rn(p0));
                    float h1f = __bfloat162float(__float2bfloat16_rn(p1));
                    float h2f = __bfloat162float(__float2bfloat16_rn(p2));
                    float h3f = __bfloat162float(__float2bfloat16_rn(p3));
                    pha[half * 2 + 0] = packbf(p0, p1);
                    pha[half * 2 + 1] = packbf(p2, p3);
                    pla[half * 2 + 0] = packbf(p0 - h0f, p1 - h1f);
                    pla[half * 2 + 1] = packbf(p2 - h2f, p3 - h3f);
                }
#pragma unroll
                for (int g = 0; g < 8; g++) {
                    uint32_t voff = swz256(kk * 16 + lrow, g * 2 + lhalf);
                    uint32_t vh4[4], vl4[4];
                    ldm_x4t(vh4, tb + 32768 + voff);
                    ldm_x4t(vl4, tb + 49152 + voff);
                    mma_bf16(O[2*g],   pha, vh4[0], vh4[1]);
                    mma_bf16(O[2*g],   pha, vl4[0], vl4[1]);
                    mma_bf16(O[2*g],   pla, vh4[0], vh4[1]);
                    mma_bf16(O[2*g+1], pha, vh4[2], vh4[3]);
                    mma_bf16(O[2*g+1], pha, vl4[2], vl4[3]);
                    mma_bf16(O[2*g+1], pla, vh4[2], vh4[3]);
                }
            }
        }
        __syncthreads();
    }

    // epilogue: normalize, split to bf16 hi/lo, store
    float il0 = 1.0f / l0, il1 = 1.0f / l1;
    size_t gr0 = (size_t)(b * T_SEQ + r0g);
    size_t gr1 = (size_t)(b * T_SEQ + r1g);
#pragma unroll
    for (int t = 0; t < 16; t++) {
        int col = h * DH + 8 * t + 2 * tig;
        float o00 = O[t][0] * il0, o01 = O[t][1] * il0;
        float o10 = O[t][2] * il1, o11 = O[t][3] * il1;
        bf16 h00 = __float2bfloat16_rn(o00), h01 = __float2bfloat16_rn(o01);
        bf16 h10 = __float2bfloat16_rn(o10), h11 = __float2bfloat16_rn(o11);
        bf16 l00 = __float2bfloat16_rn(o00 - __bfloat162float(h00));
        bf16 l01 = __float2bfloat16_rn(o01 - __bfloat162float(h01));
        bf16 l10 = __float2bfloat16_rn(o10 - __bfloat162float(h10));
        bf16 l11 = __float2bfloat16_rn(o11 - __bfloat162float(h11));
        *(__nv_bfloat162*)(aoh + gr0 * KDIM + col) = __nv_bfloat162(h00, h01);
        *(__nv_bfloat162*)(aoh + gr1 * KDIM + col) = __nv_bfloat162(h10, h11);
        *(__nv_bfloat162*)(aol + gr0 * KDIM + col) = __nv_bfloat162(l00, l01);
        *(__nv_bfloat162*)(aol + gr1 * KDIM + col) = __nv_bfloat162(l10, l11);
    }
}

// ---------------- launch ----------------
extern "C" void kernel_launch(void* const* d_in, const int* in_sizes, int n_in,
                              void* d_out, int out_size) {
    const float* x  = (const float*)d_in[0];
    const float* Wq = (const float*)d_in[1];
    const float* Wk = (const float*)d_in[2];
    const float* Wv = (const float*)d_in[3];
    const float* Wo = (const float*)d_in[4];
    float* out = (float*)d_out;

    bf16 *xhi, *xlo, *qhi, *qlo, *khi, *klo, *vhi, *vlo, *aohi, *aolo;
    bf16 *wqth, *wqtl, *wkth, *wktl, *wvth, *wvtl, *woth, *wotl;
    cudaGetSymbolAddress((void**)&xhi,  g_xhi);
    cudaGetSymbolAddress((void**)&xlo,  g_xlo);
    cudaGetSymbolAddress((void**)&qhi,  g_qhi);
    cudaGetSymbolAddress((void**)&qlo,  g_qlo);
    cudaGetSymbolAddress((void**)&khi,  g_khi);
    cudaGetSymbolAddress((void**)&klo,  g_klo);
    cudaGetSymbolAddress((void**)&vhi,  g_vhi);
    cudaGetSymbolAddress((void**)&vlo,  g_vlo);
    cudaGetSymbolAddress((void**)&aohi, g_aohi);
    cudaGetSymbolAddress((void**)&aolo, g_aolo);
    cudaGetSymbolAddress((void**)&wqth, g_wqth);
    cudaGetSymbolAddress((void**)&wqtl, g_wqtl);
    cudaGetSymbolAddress((void**)&wkth, g_wkth);
    cudaGetSymbolAddress((void**)&wktl, g_wktl);
    cudaGetSymbolAddress((void**)&wvth, g_wvth);
    cudaGetSymbolAddress((void**)&wvtl, g_wvtl);
    cudaGetSymbolAddress((void**)&woth, g_woth);
    cudaGetSymbolAddress((void**)&wotl, g_wotl);

    cudaFuncSetAttribute(tc_gemm,  cudaFuncAttributeMaxDynamicSharedMemorySize, GEMM_SMEM);
    cudaFuncSetAttribute(attn_mma, cudaFuncAttributeMaxDynamicSharedMemorySize, ATT_SMEM);

    rope_table_kernel<<<512, 256>>>();
    conv_split_kernel<<<8192, 256>>>(x, xhi, xlo);
    wtrans_kernel<<<dim3(64, 64), dim3(32, 8)>>>(Wq, wqth, wqtl, 2048);
    wtrans_kernel<<<dim3(16, 64), dim3(32, 8)>>>(Wk, wkth, wktl, 512);
    wtrans_kernel<<<dim3(16, 64), dim3(32, 8)>>>(Wv, wvth, wvtl, 512);
    wtrans_kernel<<<dim3(64, 64), dim3(32, 8)>>>(Wo, woth, wotl, 2048);

    tc_gemm<<<dim3(16, 32), 256, GEMM_SMEM>>>(xhi, xlo, wqth, wqtl,
                                              nullptr, qhi, qlo, DMODEL, 1);
    tc_gemm<<<dim3( 4, 32), 256, GEMM_SMEM>>>(xhi, xlo, wkth, wktl,
                                              nullptr, khi, klo, NKV * DH, 1);
    tc_gemm<<<dim3( 4, 32), 256, GEMM_SMEM>>>(xhi, xlo, wvth, wvtl,
                                              nullptr, vhi, vlo, NKV * DH, 0);

    attn_mma<<<dim3(16, NH, BATCH), 256, ATT_SMEM>>>(qhi, qlo, khi, klo, vhi, vlo,
                                                     aohi, aolo);

    tc_gemm<<<dim3(16, 32), 256, GEMM_SMEM>>>(aohi, aolo, woth, wotl,
                                              out, nullptr, nullptr, DMODEL, 0);
}